// round 9
// baseline (speedup 1.0000x reference)
#include <cuda_runtime.h>
#include <cuda_fp16.h>
#include <cstdint>

// ---------------------------------------------------------------------------
// HeteroSTHN head via mma.sync HMMA fp16, fp32 accum. 384 threads, 12 warps,
// 64x64 warp tiles (fat tiles -> half the LDSM bytes per MMA), NPAD=112.
// Cross-warp epilogue: src C goes through smem scratch (aliased on B bufs).
//
//   enc_src = h_src @ src_W + src_b   (bias folded as K row 200, A=1.0)
//   enc_dst = h_dst @ dst_W + dst_b
//   pred[n,t] = relu(enc_src + enc_dst) @ out_W[t] + out_b[t]
//   out[n] = masked max over t (pos);  out[E+n] = masked max over t (neg)
// ---------------------------------------------------------------------------

#define TT    8
#define DDIM  200
#define HDIM  100
#define KPAD  208            // 13 ksteps of 16 (k=200 is the bias row)
#define NPAD  112            // 7 n-groups of 16
#define BM    128
#define NTHR  384

__device__ __align__(16) uint16_t g_B[(size_t)2 * TT * KPAD * NPAD];   // 1.5 MB

// ---- smem layout (bytes) ----
#define OFF_OW   0                       // 8*112 floats = 3584
#define OFF_RED  3584                    // 2 pn * 128 e * 2 nh floats = 2048
#define OFF_BEST 5632                    // 2*128 floats = 1024
#define OFF_ANY  6656                    // 2*128 ints  = 1024
#define OFF_A    7680
#define A_ROWB   432                     // 208k*2B=416 +16 pad (27 mod 8 = 3, CF)
#define OFF_B    (OFF_A + 384 * A_ROWB)  // 173568
#define B_ROWB   240                     // 112n*2B=224 +16 pad (15 mod 8 = 7, CF)
#define B_SET    (32 * B_ROWB)           // 7680 per wm set
#define B_BUF    (2 * B_SET)             // 15360 per pipeline buffer
#define SMEM_TOTAL (OFF_B + 2 * B_BUF)   // 204288
#define OFF_SCR  OFF_B                   // 64 x 116 floats = 29696 (aliases B bufs)
#define SCR_ROWF 116

// ---------------- asm helpers ----------------
__device__ __forceinline__ uint32_t smem_u32(const void* p) {
    uint32_t a;
    asm("{ .reg .u64 t; cvta.to.shared.u64 t, %1; cvt.u32.u64 %0, t; }" : "=r"(a) : "l"(p));
    return a;
}

#define LDSM_X4(R0,R1,R2,R3,ADDR) \
    asm volatile("ldmatrix.sync.aligned.m8n8.x4.shared.b16 {%0,%1,%2,%3}, [%4];" \
        : "=r"(R0), "=r"(R1), "=r"(R2), "=r"(R3) : "r"(ADDR))

#define LDSM_X4T(R0,R1,R2,R3,ADDR) \
    asm volatile("ldmatrix.sync.aligned.m8n8.x4.trans.shared.b16 {%0,%1,%2,%3}, [%4];" \
        : "=r"(R0), "=r"(R1), "=r"(R2), "=r"(R3) : "r"(ADDR))

#define MMA4R(C, A0,A1,A2,A3, B0,B1) \
    asm volatile("mma.sync.aligned.m16n8k16.row.col.f32.f16.f16.f32 " \
        "{%0,%1,%2,%3}, {%4,%5,%6,%7}, {%8,%9}, {%0,%1,%2,%3};" \
        : "+f"((C)[0]), "+f"((C)[1]), "+f"((C)[2]), "+f"((C)[3]) \
        : "r"(A0), "r"(A1), "r"(A2), "r"(A3), "r"(B0), "r"(B1))

#define CP_ASYNC16(SMEM, GPTR) \
    asm volatile("cp.async.cg.shared.global [%0], [%1], 16;" :: "r"(SMEM), "l"(GPTR))
#define CP_COMMIT()  asm volatile("cp.async.commit_group;" ::: "memory")
#define CP_WAIT0()   asm volatile("cp.async.wait_group 0;" ::: "memory")

// ---------------- templated warp-tile helpers ----------------
template<int NG, int GB>
__device__ __forceinline__ void kstep_mma(float (&C)[4][8][4],
                                          uint32_t a_addr, uint32_t b_addr) {
    uint32_t B[4][4];
    #pragma unroll
    for (int gi = 0; gi < NG; ++gi)
        LDSM_X4T(B[gi][0], B[gi][1], B[gi][2], B[gi][3],
                 b_addr + (uint32_t)((GB + gi) * 32));
    #pragma unroll
    for (int f = 0; f < 4; ++f) {
        uint32_t A0, A1, A2, A3;
        LDSM_X4(A0, A1, A2, A3, a_addr + (uint32_t)(f * 16 * A_ROWB));
        #pragma unroll
        for (int gi = 0; gi < NG; ++gi) {
            MMA4R(C[f][2*gi],   A0, A1, A2, A3, B[gi][0], B[gi][1]);
            MMA4R(C[f][2*gi+1], A0, A1, A2, A3, B[gi][2], B[gi][3]);
        }
    }
}

template<int NJ>
__device__ __forceinline__ void zero_C(float (&C)[4][8][4]) {
    #pragma unroll
    for (int f = 0; f < 4; ++f)
        #pragma unroll
        for (int j = 0; j < NJ; ++j)
            #pragma unroll
            for (int k = 0; k < 4; ++k) C[f][j][k] = 0.0f;
}

template<int NG, int GB>
__device__ __forceinline__ void write_scratch(const float (&C)[4][8][4],
                                              float* scr, int qr, int qc) {
    #pragma unroll
    for (int f = 0; f < 4; ++f)
        #pragma unroll
        for (int j = 0; j < 2 * NG; ++j) {
            const int n = GB * 16 + j * 8 + 2 * qc;
            scr[(f*16 + qr)     * SCR_ROWF + n]     = C[f][j][0];
            scr[(f*16 + qr)     * SCR_ROWF + n + 1] = C[f][j][1];
            scr[(f*16 + 8 + qr) * SCR_ROWF + n]     = C[f][j][2];
            scr[(f*16 + 8 + qr) * SCR_ROWF + n + 1] = C[f][j][3];
        }
}

template<int NG, int GB>
__device__ __forceinline__ void consume_scratch(const float (&C)[4][8][4],
        const float* scr, const float* owt, float* redF,
        int pn, int nh, int mh, int qr, int qc) {
    float accA[4], accB[4];
    #pragma unroll
    for (int f = 0; f < 4; ++f) { accA[f] = 0.f; accB[f] = 0.f; }
    #pragma unroll
    for (int f = 0; f < 4; ++f) {
        #pragma unroll
        for (int j = 0; j < 2 * NG; ++j) {
            const int n = GB * 16 + j * 8 + 2 * qc;
            const float ow0 = owt[n], ow1 = owt[n + 1];
            const float s0 = scr[(f*16 + qr)     * SCR_ROWF + n];
            const float s1 = scr[(f*16 + qr)     * SCR_ROWF + n + 1];
            const float s2 = scr[(f*16 + 8 + qr) * SCR_ROWF + n];
            const float s3 = scr[(f*16 + 8 + qr) * SCR_ROWF + n + 1];
            accA[f] += fmaxf(s0 + C[f][j][0], 0.f) * ow0
                     + fmaxf(s1 + C[f][j][1], 0.f) * ow1;
            accB[f] += fmaxf(s2 + C[f][j][2], 0.f) * ow0
                     + fmaxf(s3 + C[f][j][3], 0.f) * ow1;
        }
    }
    #pragma unroll
    for (int f = 0; f < 4; ++f) {
        #pragma unroll
        for (int off = 1; off < 4; off <<= 1) {
            accA[f] += __shfl_xor_sync(0xffffffffu, accA[f], off);
            accB[f] += __shfl_xor_sync(0xffffffffu, accB[f], off);
        }
    }
    if (qc == 0) {
        #pragma unroll
        for (int f = 0; f < 4; ++f) {
            redF[(pn * 128 + mh*64 + f*16 + qr)     * 2 + nh] = accA[f];
            redF[(pn * 128 + mh*64 + f*16 + 8 + qr) * 2 + nh] = accB[f];
        }
    }
}

// ---------------------------------------------------------------------------
// prep B: src_W/dst_W (T,200,100) + biases -> g_B[wm][t][208][112] fp16
// ---------------------------------------------------------------------------
__global__ void prepB_kernel(const float* __restrict__ srcW, const float* __restrict__ srcb,
                             const float* __restrict__ dstW, const float* __restrict__ dstb) {
    const int gid = blockIdx.x * 256 + threadIdx.x;
    const int total = 2 * TT * KPAD * 14;
    if (gid >= total) return;
    const int nb = gid % 14;
    int rr = gid / 14;
    const int k = rr % KPAD;  rr /= KPAD;
    const int t = rr % TT;
    const int wm = rr / TT;

    const float* W  = wm ? dstW : srcW;
    const float* bb = wm ? dstb : srcb;

    __align__(16) uint16_t hb[8];
    #pragma unroll
    for (int j = 0; j < 8; ++j) {
        const int n = nb * 8 + j;
        float v = 0.0f;
        if (n < HDIM) {
            if (k < DDIM)       v = W[((size_t)t * DDIM + k) * HDIM + n];
            else if (k == DDIM) v = bb[t * HDIM + n];
        }
        const __half x = __float2half(v);
        hb[j] = *reinterpret_cast<const uint16_t*>(&x);
    }
    *reinterpret_cast<uint4*>(
        g_B + (((size_t)wm * TT + t) * KPAD + k) * NPAD + nb * 8) =
        *reinterpret_cast<uint4*>(hb);
}

// ---------------------------------------------------------------------------
// main kernel
// ---------------------------------------------------------------------------
__global__ __launch_bounds__(NTHR, 1)
void sthn_hmma_kernel(const float* __restrict__ h,
                      const float* __restrict__ outW, const float* __restrict__ outb,
                      const int* __restrict__ poss, float* __restrict__ out, int E)
{
    extern __shared__ char smem[];
    const uint32_t sb = smem_u32(smem);
    const int tid = threadIdx.x;
    const int w = tid >> 5, l = tid & 31;
    const int nh = w / 6, mt = w % 6;       // nh: n-half (0: cols 0..63, 1: 64..111)
    const int mat = mt >> 1, mh = mt & 1;   // mat 0=src 1=pos 2=neg; mh: m-half
    const int blk = blockIdx.x;

    const int lr = l & 15, lc = l >> 4;
    const int qr = l >> 2, qc = l & 3;

    // ---- B chunk issue (cp.async, one commit group) ----
    auto issueB = [&](int t, int c, int buf) {
        const int rows = (c < 6) ? 32 : 16;
        const int nops = 2 * rows * 14;
        for (int i = tid; i < nops; i += NTHR) {
            const int set = i / (rows * 14), rem = i % (rows * 14);
            const int kr = rem / 14, q = rem % 14;
            const uint16_t* src = g_B
                + (((size_t)set * TT + t) * KPAD + c * 32 + kr) * NPAD + q * 8;
            const uint32_t dst = sb + OFF_B + (uint32_t)(buf * B_BUF + set * B_SET
                                 + kr * B_ROWB + q * 16);
            CP_ASYNC16(dst, src);
        }
        CP_COMMIT();
    };

    issueB(0, 0, 0);     // first chunk in flight

    // ---- stage out_W (zero-padded); init bests ----
    {
        float* sOW = reinterpret_cast<float*>(smem + OFF_OW);
        for (int i = tid; i < TT * NPAD; i += NTHR) {
            const int t = i / NPAD, n = i % NPAD;
            sOW[i] = (n < HDIM) ? outW[t * HDIM + n] : 0.0f;
        }
        float* bestsF = reinterpret_cast<float*>(smem + OFF_BEST);
        int*   anyI   = reinterpret_cast<int*>(smem + OFF_ANY);
        for (int i = tid; i < 256; i += NTHR) { bestsF[i] = -1e30f; anyI[i] = 0; }
    }

    // ---- stage A once: fp32 h -> fp16, 384 rows x 26 groups of 8 k ----
    for (int i = tid; i < 384 * 26; i += NTHR) {
        const int row = i / 26, q = i % 26;
        const int m = row >> 7, r = row & 127;
        __align__(16) uint16_t hb[8];
        if (q < 25) {
            const float* hr = h + ((size_t)m * E + (size_t)blk * BM + r) * DDIM + q * 8;
            const float4 f0 = *reinterpret_cast<const float4*>(hr);
            const float4 f1 = *reinterpret_cast<const float4*>(hr + 4);
            *reinterpret_cast<__half2*>(hb + 0) = __floats2half2_rn(f0.x, f0.y);
            *reinterpret_cast<__half2*>(hb + 2) = __floats2half2_rn(f0.z, f0.w);
            *reinterpret_cast<__half2*>(hb + 4) = __floats2half2_rn(f1.x, f1.y);
            *reinterpret_cast<__half2*>(hb + 6) = __floats2half2_rn(f1.z, f1.w);
        } else {                             // k 200 = bias 1.0, 201..207 = 0
            hb[0] = 0x3C00; hb[1] = 0; hb[2] = 0; hb[3] = 0;
            hb[4] = 0; hb[5] = 0; hb[6] = 0; hb[7] = 0;
        }
        *reinterpret_cast<uint4*>(smem + OFF_A + row * A_ROWB + q * 16) =
            *reinterpret_cast<uint4*>(hb);
    }

    const uint32_t a_lane_base = (uint32_t)(OFF_A
        + (mat * 128 + mh * 64 + lr) * A_ROWB + lc * 16);
    const uint32_t b_lane = (uint32_t)(lr * B_ROWB + lc * 16);
    const int bset = (mat == 0) ? 0 : 1;

    float C[4][8][4];
    if (nh == 0) zero_C<8>(C); else zero_C<6>(C);

    float* scrF   = reinterpret_cast<float*>(smem + OFF_SCR);
    float* redF   = reinterpret_cast<float*>(smem + OFF_RED);
    float* bestsF = reinterpret_cast<float*>(smem + OFF_BEST);
    int*   anyI   = reinterpret_cast<int*>(smem + OFF_ANY);
    const float* sOW = reinterpret_cast<const float*>(smem + OFF_OW);

    // combine: 64 edges of (pn, phase) -> smem running max
    auto combine = [&](int pn, int phase, int t) {
        const float ob = __ldg(outb + t);
        #pragma unroll
        for (int rep = 0; rep < 2; ++rep) {
            const int e = phase * 64 + rep * 32 + l;
            const float v = redF[(pn * 128 + e) * 2 + 0]
                          + redF[(pn * 128 + e) * 2 + 1] + ob;
            const size_t eg = (size_t)(pn ? E : 0) + blk * BM + e;
            if (__ldg(poss + eg * TT + t)) {
                bestsF[pn * 128 + e] = fmaxf(bestsF[pn * 128 + e], v);
                anyI[pn * 128 + e] = 1;
            }
        }
    };

    for (int t = 0; t < TT; ++t) {
        for (int c = 0; c < 7; ++c) {
            CP_WAIT0();
            __syncthreads();
            if (c < 6) issueB(t, c + 1, (c + 1) & 1);
            const int nk = (c < 6) ? 2 : 1;
            for (int ks = 0; ks < nk; ++ks) {
                const uint32_t a_addr = sb + a_lane_base
                                        + (uint32_t)((c * 32 + ks * 16) * 2);
                const uint32_t b_addr = sb + OFF_B + (uint32_t)((c & 1) * B_BUF)
                                        + (uint32_t)(bset * B_SET)
                                        + (uint32_t)(ks * 16) * B_ROWB + b_lane;
                if (nh == 0) kstep_mma<4, 0>(C, a_addr, b_addr);
                else         kstep_mma<3, 4>(C, a_addr, b_addr);
            }
        }

        // ---- epilogue (scratch aliases B buffers; S0 guards chunk-6 readers) ----
        const float* owt = sOW + t * NPAD;
        __syncthreads();                                   // S0: all MMAs done
        if (mat == 0 && mh == 0) {
            if (nh == 0) write_scratch<4, 0>(C, scrF, qr, qc);
            else         write_scratch<3, 4>(C, scrF, qr, qc);
        }
        __syncthreads();                                   // S1
        if (mat != 0 && mh == 0) {
            const int pn = (mat == 2);
            if (nh == 0) consume_scratch<4, 0>(C, scrF, owt, redF, pn, nh, mh, qr, qc);
            else         consume_scratch<3, 4>(C, scrF, owt, redF, pn, nh, mh, qr, qc);
        }
        __syncthreads();                                   // S2
        if (w == 2) combine(0, 0, t);
        if (w == 4) combine(1, 0, t);
        if (mat == 0 && mh == 1) {
            if (nh == 0) write_scratch<4, 0>(C, scrF, qr, qc);
            else         write_scratch<3, 4>(C, scrF, qr, qc);
        }
        __syncthreads();                                   // S3
        if (mat != 0 && mh == 1) {
            const int pn = (mat == 2);
            if (nh == 0) consume_scratch<4, 0>(C, scrF, owt, redF, pn, nh, mh, qr, qc);
            else         consume_scratch<3, 4>(C, scrF, owt, redF, pn, nh, mh, qr, qc);
        }
        __syncthreads();                                   // S4
        if (t < TT - 1) issueB(t + 1, 0, 0);               // scratch free again
        if (w == 3) combine(0, 1, t);
        if (w == 5) combine(1, 1, t);

        if (nh == 0) zero_C<8>(C); else zero_C<6>(C);
    }

    __syncthreads();
    for (int i = tid; i < 256; i += NTHR) {
        const int pn = i >> 7, e = i & 127;
        out[(size_t)(pn ? E : 0) + blk * BM + e] = anyI[i] ? bestsF[i] : 0.0f;
    }
}

// ---------------------------------------------------------------------------
extern "C" void kernel_launch(void* const* d_in, const int* in_sizes, int n_in,
                              void* d_out, int out_size)
{
    const float* h    = (const float*)d_in[0];
    const float* srcW = (const float*)d_in[1];
    const float* srcb = (const float*)d_in[2];
    const float* dstW = (const float*)d_in[3];
    const float* dstb = (const float*)d_in[4];
    const float* outW = (const float*)d_in[5];
    const float* outb = (const float*)d_in[6];
    const int*   poss = (const int*)d_in[7];
    float* out = (float*)d_out;

    const int E = in_sizes[0] / (DDIM * 3);

    {
        const int totalB = 2 * TT * KPAD * 14;
        prepB_kernel<<<(totalB + 255) / 256, 256>>>(srcW, srcb, dstW, dstb);
    }

    cudaFuncSetAttribute(sthn_hmma_kernel,
                         cudaFuncAttributeMaxDynamicSharedMemorySize, SMEM_TOTAL);
    sthn_hmma_kernel<<<E / BM, NTHR, SMEM_TOTAL>>>(h, outW, outb, poss, out, E);
}

// round 10
// speedup vs baseline: 1.3994x; 1.3994x over previous
#include <cuda_runtime.h>
#include <cuda_fp16.h>
#include <cstdint>

// ---------------------------------------------------------------------------
// HeteroSTHN head via mma.sync HMMA fp16 (fp32 accum). R8 skeleton:
// 512 threads, warp (mw, nw): m-rows [mw*16,+16) of all 3 matrices,
// n-half nw*56 (NPAD=112, balanced 56/56 via x4T+x2T ldmatrix).
// Double-buffered cp.async B pipeline, 48-krow chunks (5 per t).
//
//   enc_src = h_src @ src_W + src_b   (bias folded as K row 200, A=1.0)
//   enc_dst = h_dst @ dst_W + dst_b
//   pred[n,t] = relu(enc_src + enc_dst) @ out_W[t] + out_b[t]
//   out[n] = masked max over t (pos);  out[E+n] = masked max over t (neg)
// ---------------------------------------------------------------------------

#define TT    8
#define DDIM  200
#define HDIM  100
#define KPAD  208            // 13 ksteps of 16 (k=200 is the bias row)
#define NPAD  112            // 14 n-frags of 8
#define BM    128
#define NTHR  512

__device__ __align__(16) uint16_t g_B[(size_t)2 * TT * KPAD * NPAD];   // 1.5 MB

// ---- smem layout (bytes) ----
#define OFF_OW   0                       // 8*112 floats = 3584
#define OFF_RED  3584                    // 8 mw * 8 qr * 4 floats = 1024
#define OFF_A    4608
#define A_ROWB   432                     // 208k*2B=416 +16 pad (conflict-free)
#define A_SZ     (384 * A_ROWB)          // 165888
#define OFF_B    (OFF_A + A_SZ)          // 170496
#define B_ROWB   240                     // 112n*2B=224 +16 pad (conflict-free)
#define B_SET    (48 * B_ROWB)           // 11520 per wm set (48 k-rows)
#define B_BUF    (2 * B_SET)             // 23040 per pipeline buffer
#define SMEM_TOTAL (OFF_B + 2 * B_BUF)   // 216576

#define NCHUNK  5                        // 4 x 48 + 1 x 16 k-rows
#define NCT     (TT * NCHUNK)            // 40 pipeline steps

// ---------------- asm helpers ----------------
__device__ __forceinline__ uint32_t smem_u32(const void* p) {
    uint32_t a;
    asm("{ .reg .u64 t; cvta.to.shared.u64 t, %1; cvt.u32.u64 %0, t; }" : "=r"(a) : "l"(p));
    return a;
}

#define LDSM_X4(R0,R1,R2,R3,ADDR) \
    asm volatile("ldmatrix.sync.aligned.m8n8.x4.shared.b16 {%0,%1,%2,%3}, [%4];" \
        : "=r"(R0), "=r"(R1), "=r"(R2), "=r"(R3) : "r"(ADDR))

#define LDSM_X4T(R0,R1,R2,R3,ADDR) \
    asm volatile("ldmatrix.sync.aligned.m8n8.x4.trans.shared.b16 {%0,%1,%2,%3}, [%4];" \
        : "=r"(R0), "=r"(R1), "=r"(R2), "=r"(R3) : "r"(ADDR))

#define LDSM_X2T(R0,R1,ADDR) \
    asm volatile("ldmatrix.sync.aligned.m8n8.x2.trans.shared.b16 {%0,%1}, [%2];" \
        : "=r"(R0), "=r"(R1) : "r"(ADDR))

#define MMA4(C, A, B0, B1) \
    asm volatile("mma.sync.aligned.m16n8k16.row.col.f32.f16.f16.f32 " \
        "{%0,%1,%2,%3}, {%4,%5,%6,%7}, {%8,%9}, {%0,%1,%2,%3};" \
        : "+f"((C)[0]), "+f"((C)[1]), "+f"((C)[2]), "+f"((C)[3]) \
        : "r"((A)[0]), "r"((A)[1]), "r"((A)[2]), "r"((A)[3]), "r"(B0), "r"(B1))

#define CP_ASYNC16(SMEM, GPTR) \
    asm volatile("cp.async.cg.shared.global [%0], [%1], 16;" :: "r"(SMEM), "l"(GPTR))
#define CP_COMMIT()  asm volatile("cp.async.commit_group;" ::: "memory")
#define CP_WAIT0()   asm volatile("cp.async.wait_group 0;" ::: "memory")

// ---------------------------------------------------------------------------
// prep B: src_W/dst_W (T,200,100) + biases -> g_B[wm][t][208][112] fp16,
// k-major rows of n (for ldmatrix.trans); bias at k==200; zero padding
// ---------------------------------------------------------------------------
__global__ void prepB_kernel(const float* __restrict__ srcW, const float* __restrict__ srcb,
                             const float* __restrict__ dstW, const float* __restrict__ dstb) {
    const int gid = blockIdx.x * 256 + threadIdx.x;
    const int total = 2 * TT * KPAD * 14;
    if (gid >= total) return;
    const int nb = gid % 14;
    int rr = gid / 14;
    const int k = rr % KPAD;  rr /= KPAD;
    const int t = rr % TT;
    const int wm = rr / TT;

    const float* W  = wm ? dstW : srcW;
    const float* bb = wm ? dstb : srcb;

    __align__(16) uint16_t hb[8];
    #pragma unroll
    for (int j = 0; j < 8; ++j) {
        const int n = nb * 8 + j;
        float v = 0.0f;
        if (n < HDIM) {
            if (k < DDIM)       v = W[((size_t)t * DDIM + k) * HDIM + n];
            else if (k == DDIM) v = bb[t * HDIM + n];
        }
        const __half x = __float2half(v);
        hb[j] = *reinterpret_cast<const uint16_t*>(&x);
    }
    *reinterpret_cast<uint4*>(
        g_B + (((size_t)wm * TT + t) * KPAD + k) * NPAD + nb * 8) =
        *reinterpret_cast<uint4*>(hb);
}

// ---------------------------------------------------------------------------
// main kernel
// ---------------------------------------------------------------------------
__global__ __launch_bounds__(NTHR, 1)
void sthn_hmma_kernel(const float* __restrict__ h,
                      const float* __restrict__ outW, const float* __restrict__ outb,
                      const int* __restrict__ poss, float* __restrict__ out, int E)
{
    extern __shared__ char smem[];
    const uint32_t sb = smem_u32(smem);
    const int tid = threadIdx.x;
    const int w = tid >> 5, l = tid & 31;
    const int mw = w >> 1, nw = w & 1;
    const int blk = blockIdx.x;

    // ---- B chunk issue helper (cp.async, one commit group) ----
    auto issueB = [&](int ct, int buf) {
        const int t = ct / NCHUNK, c = ct % NCHUNK;
        const int rows = (c < 4) ? 48 : 16;
        const int nops = 2 * rows * 14;
        for (int i = tid; i < nops; i += NTHR) {
            const int set = i / (rows * 14), rem = i % (rows * 14);
            const int kr = rem / 14, q = rem % 14;
            const uint16_t* src = g_B
                + (((size_t)set * TT + t) * KPAD + c * 48 + kr) * NPAD + q * 8;
            const uint32_t dst = sb + OFF_B + (uint32_t)(buf * B_BUF + set * B_SET
                                 + kr * B_ROWB + q * 16);
            CP_ASYNC16(dst, src);
        }
        CP_COMMIT();
    };

    // ---- stage out_W (zero-padded) ----
    {
        float* sOW = reinterpret_cast<float*>(smem + OFF_OW);
        for (int i = tid; i < TT * NPAD; i += NTHR) {
            const int t = i / NPAD, n = i % NPAD;
            sOW[i] = (n < HDIM) ? outW[t * HDIM + n] : 0.0f;
        }
    }
    issueB(0, 0);     // first chunk in flight

    // ---- stage A once: fp32 h -> fp16, 384 rows x 26 groups of 8 k ----
    for (int i = tid; i < 384 * 26; i += NTHR) {
        const int row = i / 26, q = i % 26;
        const int m = row >> 7, r = row & 127;
        __align__(16) uint16_t hb[8];
        if (q < 25) {
            const float* hr = h + ((size_t)m * E + (size_t)blk * BM + r) * DDIM + q * 8;
            const float4 f0 = *reinterpret_cast<const float4*>(hr);
            const float4 f1 = *reinterpret_cast<const float4*>(hr + 4);
            *reinterpret_cast<__half2*>(hb + 0) = __floats2half2_rn(f0.x, f0.y);
            *reinterpret_cast<__half2*>(hb + 2) = __floats2half2_rn(f0.z, f0.w);
            *reinterpret_cast<__half2*>(hb + 4) = __floats2half2_rn(f1.x, f1.y);
            *reinterpret_cast<__half2*>(hb + 6) = __floats2half2_rn(f1.z, f1.w);
        } else {                             // k 200 = bias 1.0, 201..207 = 0
            hb[0] = 0x3C00; hb[1] = 0; hb[2] = 0; hb[3] = 0;
            hb[4] = 0; hb[5] = 0; hb[6] = 0; hb[7] = 0;
        }
        *reinterpret_cast<uint4*>(smem + OFF_A + row * A_ROWB + q * 16) =
            *reinterpret_cast<uint4*>(hb);
    }

    const int lr = l & 15, lc = l >> 4;            // ldmatrix lane addressing
    const int qr = l >> 2, qc = l & 3;             // C-fragment row/col in quad
    const uint32_t a_lane = (uint32_t)((mw * 16 + lr) * A_ROWB + lc * 16);
    // B lane: this warp's n-window starts at col nw*56 (112 bytes)
    const uint32_t b_lane4 = (uint32_t)(lr * B_ROWB + lc * 16 + nw * 112);
    const uint32_t b_lane2 = (uint32_t)(lr * B_ROWB + nw * 112 + 96);

    float bests[4] = {-1e30f, -1e30f, -1e30f, -1e30f};
    int   anys[4]  = {0, 0, 0, 0};

    // C[m][frag 0..6][4]; this warp's n-cols = nw*56 + nf*8
    float C[3][7][4];
    #pragma unroll
    for (int m = 0; m < 3; ++m)
        #pragma unroll
        for (int nf = 0; nf < 7; ++nf)
            #pragma unroll
            for (int j = 0; j < 4; ++j) C[m][nf][j] = 0.0f;

    float* sRED = reinterpret_cast<float*>(smem + OFF_RED);

    for (int ct = 0; ct < NCT; ++ct) {
        const int t = ct / NCHUNK, c = ct % NCHUNK;
        const int buf = ct & 1;

        CP_WAIT0();
        __syncthreads();

        if (ct + 1 < NCT) issueB(ct + 1, buf ^ 1);

        const int nk = (c < 4) ? 3 : 1;
        const uint32_t bbase = sb + OFF_B + (uint32_t)(buf * B_BUF);
        for (int ks = 0; ks < nk; ++ks) {
            const uint32_t kb = (uint32_t)(c * 48 + ks * 16) * 2;
            uint32_t Ah[3][4];
            #pragma unroll
            for (int m = 0; m < 3; ++m) {
                const uint32_t aa = sb + OFF_A + (uint32_t)(m * 128 * A_ROWB)
                                    + a_lane + kb;
                LDSM_X4(Ah[m][0], Ah[m][1], Ah[m][2], Ah[m][3], aa);
            }
            const uint32_t brow = bbase + (uint32_t)(ks * 16) * B_ROWB;
            #pragma unroll
            for (int g = 0; g < 3; ++g) {
                uint32_t b0[4], b1[4];
                LDSM_X4T(b0[0], b0[1], b0[2], b0[3],
                         brow + b_lane4 + (uint32_t)g * 32);            // srcW
                LDSM_X4T(b1[0], b1[1], b1[2], b1[3],
                         brow + b_lane4 + (uint32_t)g * 32 + B_SET);    // dstW
                MMA4(C[0][2*g],   Ah[0], b0[0], b0[1]);
                MMA4(C[0][2*g+1], Ah[0], b0[2], b0[3]);
                MMA4(C[1][2*g],   Ah[1], b1[0], b1[1]);
                MMA4(C[1][2*g+1], Ah[1], b1[2], b1[3]);
                MMA4(C[2][2*g],   Ah[2], b1[0], b1[1]);
                MMA4(C[2][2*g+1], Ah[2], b1[2], b1[3]);
            }
            {   // last 8 cols of this warp's 56-col window
                uint32_t c0[2], c1[2];
                LDSM_X2T(c0[0], c0[1], brow + b_lane2);
                LDSM_X2T(c1[0], c1[1], brow + b_lane2 + B_SET);
                MMA4(C[0][6], Ah[0], c0[0], c0[1]);
                MMA4(C[1][6], Ah[1], c1[0], c1[1]);
                MMA4(C[2][6], Ah[2], c1[0], c1[1]);
            }
        }

        if (c == NCHUNK - 1) {
            // ---- epilogue for t ----
            float pl = 0.f, ph = 0.f, nl = 0.f, nh = 0.f;
            const float* ow = reinterpret_cast<const float*>(smem + OFF_OW)
                              + t * NPAD + nw * 56;
            const int col0 = 2 * qc;
            #pragma unroll
            for (int nf = 0; nf < 7; ++nf) {
                const float ow0 = ow[nf * 8 + col0];
                const float ow1 = ow[nf * 8 + col0 + 1];
                pl += fmaxf(C[0][nf][0] + C[1][nf][0], 0.f) * ow0
                    + fmaxf(C[0][nf][1] + C[1][nf][1], 0.f) * ow1;
                ph += fmaxf(C[0][nf][2] + C[1][nf][2], 0.f) * ow0
                    + fmaxf(C[0][nf][3] + C[1][nf][3], 0.f) * ow1;
                nl += fmaxf(C[0][nf][0] + C[2][nf][0], 0.f) * ow0
                    + fmaxf(C[0][nf][1] + C[2][nf][1], 0.f) * ow1;
                nh += fmaxf(C[0][nf][2] + C[2][nf][2], 0.f) * ow0
                    + fmaxf(C[0][nf][3] + C[2][nf][3], 0.f) * ow1;
            }
            #pragma unroll
            for (int off = 1; off < 4; off <<= 1) {
                pl += __shfl_xor_sync(0xffffffffu, pl, off);
                ph += __shfl_xor_sync(0xffffffffu, ph, off);
                nl += __shfl_xor_sync(0xffffffffu, nl, off);
                nh += __shfl_xor_sync(0xffffffffu, nh, off);
            }

            if (nw == 0 && qc == 0) {
                float* dst = sRED + (mw * 8 + qr) * 4;
                dst[0] = pl; dst[1] = ph; dst[2] = nl; dst[3] = nh;
            }
            __syncthreads();
            if (nw == 1 && qc == 0) {
                const float* ptn = sRED + (mw * 8 + qr) * 4;
                const float tpl = pl + ptn[0];
                const float tph = ph + ptn[1];
                const float tnl = nl + ptn[2];
                const float tnh = nh + ptn[3];

                const float ob = __ldg(outb + t);
                const int e_lo = blk * BM + mw * 16 + qr;
                const int e_hi = e_lo + 8;
                const int mpl = __ldg(poss + (size_t)e_lo * TT + t);
                const int mph = __ldg(poss + (size_t)e_hi * TT + t);
                const int mnl = __ldg(poss + ((size_t)E + e_lo) * TT + t);
                const int mnh = __ldg(poss + ((size_t)E + e_hi) * TT + t);
                if (mpl) { bests[0] = fmaxf(bests[0], tpl + ob); anys[0] = 1; }
                if (mph) { bests[1] = fmaxf(bests[1], tph + ob); anys[1] = 1; }
                if (mnl) { bests[2] = fmaxf(bests[2], tnl + ob); anys[2] = 1; }
                if (mnh) { bests[3] = fmaxf(bests[3], tnh + ob); anys[3] = 1; }
            }

            #pragma unroll
            for (int m = 0; m < 3; ++m)
                #pragma unroll
                for (int nf = 0; nf < 7; ++nf)
                    #pragma unroll
                    for (int j = 0; j < 4; ++j) C[m][nf][j] = 0.0f;
        }
    }

    if (nw == 1 && qc == 0) {
        const int e_lo = blk * BM + mw * 16 + qr;
        const int e_hi = e_lo + 8;
        out[e_lo]     = anys[0] ? bests[0] : 0.0f;
        out[e_hi]     = anys[1] ? bests[1] : 0.0f;
        out[E + e_lo] = anys[2] ? bests[2] : 0.0f;
        out[E + e_hi] = anys[3] ? bests[3] : 0.0f;
    }
}

// ---------------------------------------------------------------------------
extern "C" void kernel_launch(void* const* d_in, const int* in_sizes, int n_in,
                              void* d_out, int out_size)
{
    const float* h    = (const float*)d_in[0];
    const float* srcW = (const float*)d_in[1];
    const float* srcb = (const float*)d_in[2];
    const float* dstW = (const float*)d_in[3];
    const float* dstb = (const float*)d_in[4];
    const float* outW = (const float*)d_in[5];
    const float* outb = (const float*)d_in[6];
    const int*   poss = (const int*)d_in[7];
    float* out = (float*)d_out;

    const int E = in_sizes[0] / (DDIM * 3);

    {
        const int totalB = 2 * TT * KPAD * 14;
        prepB_kernel<<<(totalB + 255) / 256, 256>>>(srcW, srcb, dstW, dstb);
    }

    cudaFuncSetAttribute(sthn_hmma_kernel,
                         cudaFuncAttributeMaxDynamicSharedMemorySize, SMEM_TOTAL);
    sthn_hmma_kernel<<<E / BM, NTHR, SMEM_TOTAL>>>(h, outW, outb, poss, out, E);
}

// round 11
// speedup vs baseline: 1.5394x; 1.1001x over previous
#include <cuda_runtime.h>
#include <cuda_fp16.h>
#include <cstdint>

// ---------------------------------------------------------------------------
// HeteroSTHN head via mma.sync HMMA fp16 (fp32 accum).
// BM=64, 256 threads, 8 warps: warp (mw, nw) owns m-rows [mw*16,+16) of all
// 3 matrices x n-half nw*56 (NPAD=112). Double-buffered cp.async B pipeline
// (32-krow chunks). Small smem (111.5 KB) -> 2 CTAs/SM for cross-CTA overlap.
//
//   enc_src = h_src @ src_W + src_b   (bias folded as K row 200, A=1.0)
//   enc_dst = h_dst @ dst_W + dst_b
//   pred[n,t] = relu(enc_src + enc_dst) @ out_W[t] + out_b[t]
//   out[n] = masked max over t (pos);  out[E+n] = masked max over t (neg)
// ---------------------------------------------------------------------------

#define TT    8
#define DDIM  200
#define HDIM  100
#define KPAD  208            // 13 ksteps of 16 (k=200 is the bias row)
#define NPAD  112            // 14 n-frags of 8
#define BM    64
#define NTHR  256

__device__ __align__(16) uint16_t g_B[(size_t)2 * TT * KPAD * NPAD];   // 1.5 MB

// ---- smem layout (bytes) ----
#define OFF_RED  0                       // 4 mw * 8 qr * 4 floats = 512
#define OFF_A    512
#define A_ROWB   432                     // 208k*2B=416 +16 pad (conflict-free)
#define A_SZ     (192 * A_ROWB)          // 82944 (3 mats x 64 rows)
#define OFF_B    (OFF_A + A_SZ)          // 83456
#define B_ROWB   240                     // 112n*2B=224 +16 pad (conflict-free)
#define B_SET    (32 * B_ROWB)           // 7680 per wm set (32 k-rows)
#define B_BUF    (2 * B_SET)             // 15360 per pipeline buffer
#define SMEM_TOTAL (OFF_B + 2 * B_BUF)   // 114176  (2 CTAs/SM)

#define NCHUNK  7                        // 6 x 32 + 1 x 16 k-rows
#define NCT     (TT * NCHUNK)            // 56 pipeline steps

// ---------------- asm helpers ----------------
__device__ __forceinline__ uint32_t smem_u32(const void* p) {
    uint32_t a;
    asm("{ .reg .u64 t; cvta.to.shared.u64 t, %1; cvt.u32.u64 %0, t; }" : "=r"(a) : "l"(p));
    return a;
}

#define LDSM_X4(R0,R1,R2,R3,ADDR) \
    asm volatile("ldmatrix.sync.aligned.m8n8.x4.shared.b16 {%0,%1,%2,%3}, [%4];" \
        : "=r"(R0), "=r"(R1), "=r"(R2), "=r"(R3) : "r"(ADDR))

#define LDSM_X4T(R0,R1,R2,R3,ADDR) \
    asm volatile("ldmatrix.sync.aligned.m8n8.x4.trans.shared.b16 {%0,%1,%2,%3}, [%4];" \
        : "=r"(R0), "=r"(R1), "=r"(R2), "=r"(R3) : "r"(ADDR))

#define LDSM_X2T(R0,R1,ADDR) \
    asm volatile("ldmatrix.sync.aligned.m8n8.x2.trans.shared.b16 {%0,%1}, [%2];" \
        : "=r"(R0), "=r"(R1) : "r"(ADDR))

#define MMA4(C, A, B0, B1) \
    asm volatile("mma.sync.aligned.m16n8k16.row.col.f32.f16.f16.f32 " \
        "{%0,%1,%2,%3}, {%4,%5,%6,%7}, {%8,%9}, {%0,%1,%2,%3};" \
        : "+f"((C)[0]), "+f"((C)[1]), "+f"((C)[2]), "+f"((C)[3]) \
        : "r"((A)[0]), "r"((A)[1]), "r"((A)[2]), "r"((A)[3]), "r"(B0), "r"(B1))

#define CP_ASYNC16(SMEM, GPTR) \
    asm volatile("cp.async.cg.shared.global [%0], [%1], 16;" :: "r"(SMEM), "l"(GPTR))
#define CP_COMMIT()  asm volatile("cp.async.commit_group;" ::: "memory")
#define CP_WAIT0()   asm volatile("cp.async.wait_group 0;" ::: "memory")

// ---------------------------------------------------------------------------
// prep B: src_W/dst_W (T,200,100) + biases -> g_B[wm][t][208][112] fp16,
// k-major rows of n (for ldmatrix.trans); bias at k==200; zero padding
// ---------------------------------------------------------------------------
__global__ void prepB_kernel(const float* __restrict__ srcW, const float* __restrict__ srcb,
                             const float* __restrict__ dstW, const float* __restrict__ dstb) {
    const int gid = blockIdx.x * 256 + threadIdx.x;
    const int total = 2 * TT * KPAD * 14;
    if (gid >= total) return;
    const int nb = gid % 14;
    int rr = gid / 14;
    const int k = rr % KPAD;  rr /= KPAD;
    const int t = rr % TT;
    const int wm = rr / TT;

    const float* W  = wm ? dstW : srcW;
    const float* bb = wm ? dstb : srcb;

    __align__(16) uint16_t hb[8];
    #pragma unroll
    for (int j = 0; j < 8; ++j) {
        const int n = nb * 8 + j;
        float v = 0.0f;
        if (n < HDIM) {
            if (k < DDIM)       v = W[((size_t)t * DDIM + k) * HDIM + n];
            else if (k == DDIM) v = bb[t * HDIM + n];
        }
        const __half x = __float2half(v);
        hb[j] = *reinterpret_cast<const uint16_t*>(&x);
    }
    *reinterpret_cast<uint4*>(
        g_B + (((size_t)wm * TT + t) * KPAD + k) * NPAD + nb * 8) =
        *reinterpret_cast<uint4*>(hb);
}

// ---------------------------------------------------------------------------
// main kernel
// ---------------------------------------------------------------------------
__global__ __launch_bounds__(NTHR, 2)
void sthn_hmma_kernel(const float* __restrict__ h,
                      const float* __restrict__ outW, const float* __restrict__ outb,
                      const int* __restrict__ poss, float* __restrict__ out, int E)
{
    extern __shared__ char smem[];
    const uint32_t sb = smem_u32(smem);
    const int tid = threadIdx.x;
    const int w = tid >> 5, l = tid & 31;
    const int mw = w >> 1, nw = w & 1;
    const int blk = blockIdx.x;

    // ---- B chunk issue helper (cp.async, one commit group) ----
    auto issueB = [&](int ct, int buf) {
        const int t = ct / NCHUNK, c = ct % NCHUNK;
        const int rows = (c < 6) ? 32 : 16;
        const int nops = 2 * rows * 14;
        for (int i = tid; i < nops; i += NTHR) {
            const int set = i / (rows * 14), rem = i % (rows * 14);
            const int kr = rem / 14, q = rem % 14;
            const uint16_t* src = g_B
                + (((size_t)set * TT + t) * KPAD + c * 32 + kr) * NPAD + q * 8;
            const uint32_t dst = sb + OFF_B + (uint32_t)(buf * B_BUF + set * B_SET
                                 + kr * B_ROWB + q * 16);
            CP_ASYNC16(dst, src);
        }
        CP_COMMIT();
    };

    issueB(0, 0);     // first chunk in flight

    // ---- stage A once: fp32 h -> fp16, 192 rows x 26 groups of 8 k ----
    for (int i = tid; i < 192 * 26; i += NTHR) {
        const int row = i / 26, q = i % 26;
        const int m = row >> 6, r = row & 63;
        __align__(16) uint16_t hb[8];
        if (q < 25) {
            const float* hr = h + ((size_t)m * E + (size_t)blk * BM + r) * DDIM + q * 8;
            const float4 f0 = *reinterpret_cast<const float4*>(hr);
            const float4 f1 = *reinterpret_cast<const float4*>(hr + 4);
            *reinterpret_cast<__half2*>(hb + 0) = __floats2half2_rn(f0.x, f0.y);
            *reinterpret_cast<__half2*>(hb + 2) = __floats2half2_rn(f0.z, f0.w);
            *reinterpret_cast<__half2*>(hb + 4) = __floats2half2_rn(f1.x, f1.y);
            *reinterpret_cast<__half2*>(hb + 6) = __floats2half2_rn(f1.z, f1.w);
        } else {                             // k 200 = bias 1.0, 201..207 = 0
            hb[0] = 0x3C00; hb[1] = 0; hb[2] = 0; hb[3] = 0;
            hb[4] = 0; hb[5] = 0; hb[6] = 0; hb[7] = 0;
        }
        *reinterpret_cast<uint4*>(smem + OFF_A + row * A_ROWB + q * 16) =
            *reinterpret_cast<uint4*>(hb);
    }

    const int lr = l & 15, lc = l >> 4;            // ldmatrix lane addressing
    const int qr = l >> 2, qc = l & 3;             // C-fragment row/col in quad
    const uint32_t a_lane = (uint32_t)((mw * 16 + lr) * A_ROWB + lc * 16);
    // B lane: this warp's n-window starts at col nw*56 (112 bytes)
    const uint32_t b_lane4 = (uint32_t)(lr * B_ROWB + lc * 16 + nw * 112);
    const uint32_t b_lane2 = (uint32_t)(lr * B_ROWB + nw * 112 + 96);

    float bests[4] = {-1e30f, -1e30f, -1e30f, -1e30f};
    int   anys[4]  = {0, 0, 0, 0};

    // C[m][frag 0..6][4]; this warp's n-cols = nw*56 + nf*8
    float C[3][7][4];
    #pragma unroll
    for (int m = 0; m < 3; ++m)
        #pragma unroll
        for (int nf = 0; nf < 7; ++nf)
            #pragma unroll
            for (int j = 0; j < 4; ++j) C[m][nf][j] = 0.0f;

    float* sRED = reinterpret_cast<float*>(smem + OFF_RED);

    for (int ct = 0; ct < NCT; ++ct) {
        const int t = ct / NCHUNK, c = ct % NCHUNK;
        const int buf = ct & 1;

        CP_WAIT0();
        __syncthreads();

        if (ct + 1 < NCT) issueB(ct + 1, buf ^ 1);

        const int nk = (c < 6) ? 2 : 1;
        const uint32_t bbase = sb + OFF_B + (uint32_t)(buf * B_BUF);
        for (int ks = 0; ks < nk; ++ks) {
            const uint32_t kb = (uint32_t)(c * 32 + ks * 16) * 2;
            uint32_t Ah[3][4];
            #pragma unroll
            for (int m = 0; m < 3; ++m) {
                const uint32_t aa = sb + OFF_A + (uint32_t)(m * 64 * A_ROWB)
                                    + a_lane + kb;
                LDSM_X4(Ah[m][0], Ah[m][1], Ah[m][2], Ah[m][3], aa);
            }
            const uint32_t brow = bbase + (uint32_t)(ks * 16) * B_ROWB;
            #pragma unroll
            for (int g = 0; g < 3; ++g) {
                uint32_t b0[4], b1[4];
                LDSM_X4T(b0[0], b0[1], b0[2], b0[3],
                         brow + b_lane4 + (uint32_t)g * 32);            // srcW
                LDSM_X4T(b1[0], b1[1], b1[2], b1[3],
                         brow + b_lane4 + (uint32_t)g * 32 + B_SET);    // dstW
                MMA4(C[0][2*g],   Ah[0], b0[0], b0[1]);
                MMA4(C[0][2*g+1], Ah[0], b0[2], b0[3]);
                MMA4(C[1][2*g],   Ah[1], b1[0], b1[1]);
                MMA4(C[1][2*g+1], Ah[1], b1[2], b1[3]);
                MMA4(C[2][2*g],   Ah[2], b1[0], b1[1]);
                MMA4(C[2][2*g+1], Ah[2], b1[2], b1[3]);
            }
            {   // last 8 cols of this warp's 56-col window
                uint32_t c0[2], c1[2];
                LDSM_X2T(c0[0], c0[1], brow + b_lane2);
                LDSM_X2T(c1[0], c1[1], brow + b_lane2 + B_SET);
                MMA4(C[0][6], Ah[0], c0[0], c0[1]);
                MMA4(C[1][6], Ah[1], c1[0], c1[1]);
                MMA4(C[2][6], Ah[2], c1[0], c1[1]);
            }
        }

        if (c == NCHUNK - 1) {
            // ---- epilogue for t (out_W via __ldg; cols >= HDIM contribute 0) ----
            float pl = 0.f, ph = 0.f, nl = 0.f, nh = 0.f;
            const float* owg = outW + t * HDIM;
            const int col0 = nw * 56 + 2 * qc;
            #pragma unroll
            for (int nf = 0; nf < 7; ++nf) {
                const int n0 = col0 + nf * 8;
                const float ow0 = (n0     < HDIM) ? __ldg(owg + n0)     : 0.0f;
                const float ow1 = (n0 + 1 < HDIM) ? __ldg(owg + n0 + 1) : 0.0f;
                pl += fmaxf(C[0][nf][0] + C[1][nf][0], 0.f) * ow0
                    + fmaxf(C[0][nf][1] + C[1][nf][1], 0.f) * ow1;
                ph += fmaxf(C[0][nf][2] + C[1][nf][2], 0.f) * ow0
                    + fmaxf(C[0][nf][3] + C[1][nf][3], 0.f) * ow1;
                nl += fmaxf(C[0][nf][0] + C[2][nf][0], 0.f) * ow0
                    + fmaxf(C[0][nf][1] + C[2][nf][1], 0.f) * ow1;
                nh += fmaxf(C[0][nf][2] + C[2][nf][2], 0.f) * ow0
                    + fmaxf(C[0][nf][3] + C[2][nf][3], 0.f) * ow1;
            }
            #pragma unroll
            for (int off = 1; off < 4; off <<= 1) {
                pl += __shfl_xor_sync(0xffffffffu, pl, off);
                ph += __shfl_xor_sync(0xffffffffu, ph, off);
                nl += __shfl_xor_sync(0xffffffffu, nl, off);
                nh += __shfl_xor_sync(0xffffffffu, nh, off);
            }

            if (nw == 0 && qc == 0) {
                float* dst = sRED + (mw * 8 + qr) * 4;
                dst[0] = pl; dst[1] = ph; dst[2] = nl; dst[3] = nh;
            }
            __syncthreads();
            if (nw == 1 && qc == 0) {
                const float* ptn = sRED + (mw * 8 + qr) * 4;
                const float tpl = pl + ptn[0];
                const float tph = ph + ptn[1];
                const float tnl = nl + ptn[2];
                const float tnh = nh + ptn[3];

                const float ob = __ldg(outb + t);
                const int e_lo = blk * BM + mw * 16 + qr;
                const int e_hi = e_lo + 8;
                const int mpl = __ldg(poss + (size_t)e_lo * TT + t);
                const int mph = __ldg(poss + (size_t)e_hi * TT + t);
                const int mnl = __ldg(poss + ((size_t)E + e_lo) * TT + t);
                const int mnh = __ldg(poss + ((size_t)E + e_hi) * TT + t);
                if (mpl) { bests[0] = fmaxf(bests[0], tpl + ob); anys[0] = 1; }
                if (mph) { bests[1] = fmaxf(bests[1], tph + ob); anys[1] = 1; }
                if (mnl) { bests[2] = fmaxf(bests[2], tnl + ob); anys[2] = 1; }
                if (mnh) { bests[3] = fmaxf(bests[3], tnh + ob); anys[3] = 1; }
            }

            #pragma unroll
            for (int m = 0; m < 3; ++m)
                #pragma unroll
                for (int nf = 0; nf < 7; ++nf)
                    #pragma unroll
                    for (int j = 0; j < 4; ++j) C[m][nf][j] = 0.0f;
        }
    }

    if (nw == 1 && qc == 0) {
        const int e_lo = blk * BM + mw * 16 + qr;
        const int e_hi = e_lo + 8;
        out[e_lo]     = anys[0] ? bests[0] : 0.0f;
        out[e_hi]     = anys[1] ? bests[1] : 0.0f;
        out[E + e_lo] = anys[2] ? bests[2] : 0.0f;
        out[E + e_hi] = anys[3] ? bests[3] : 0.0f;
    }
}

// ---------------------------------------------------------------------------
extern "C" void kernel_launch(void* const* d_in, const int* in_sizes, int n_in,
                              void* d_out, int out_size)
{
    const float* h    = (const float*)d_in[0];
    const float* srcW = (const float*)d_in[1];
    const float* srcb = (const float*)d_in[2];
    const float* dstW = (const float*)d_in[3];
    const float* dstb = (const float*)d_in[4];
    const float* outW = (const float*)d_in[5];
    const float* outb = (const float*)d_in[6];
    const int*   poss = (const int*)d_in[7];
    float* out = (float*)d_out;

    const int E = in_sizes[0] / (DDIM * 3);

    {
        const int totalB = 2 * TT * KPAD * 14;
        prepB_kernel<<<(totalB + 255) / 256, 256>>>(srcW, srcb, dstW, dstb);
    }

    cudaFuncSetAttribute(sthn_hmma_kernel,
                         cudaFuncAttributeMaxDynamicSharedMemorySize, SMEM_TOTAL);
    sthn_hmma_kernel<<<E / BM, NTHR, SMEM_TOTAL>>>(h, outW, outb, poss, out, E);
}